// round 5
// baseline (speedup 1.0000x reference)
#include <cuda_runtime.h>

// _QuantumLSTMCell: analytic collapse of the 4-qubit circuit.
// angles = comb @ W^T + b ; z_w = cos(angle_w + th_w)
// E0 = z1 z2 z3 ; E1 = z0 z1 ; E2 = z0 z1 z2 ; E3 = z0 z1 z2 z3
// f,i,o = sigmoid(E), g = tanh(E_u); c' = f*cx + i*g; h' = o*tanh(c')
// out = [h_new (B*4) | c_new (B*4)]
//
// R5: RPT=2 (grid 512, ~12 warps/SM vs 6.9) to fix grid-limited occupancy;
// cp.async double-buffered x staging kept; j-major weight LDS kept.

#define THREADS 128
#define RPT 2
#define ROWS_BLK (THREADS * RPT)     // 256
#define D_COLS 256
#define NJ 16
#define TILE_K 16
#define NTILES (D_COLS / TILE_K)     // 16
#define PITCH 20                     // floats per staged row (80 B)
#define XS_STAGE_F (ROWS_BLK * PITCH)   // 5120 floats per stage
#define SWF_F (260 * NJ)             // 4160 floats
#define SMEM_FLOATS (SWF_F + 2 * XS_STAGE_F + NJ)
#define SMEM_BYTES (SMEM_FLOATS * 4) // 57,888 B -> 3 blocks/SM

typedef unsigned long long u64;

__device__ __forceinline__ u64 pk(float lo, float hi) {
    u64 r; asm("mov.b64 %0, {%1,%2};" : "=l"(r) : "f"(lo), "f"(hi)); return r;
}
__device__ __forceinline__ void upk(u64 v, float& lo, float& hi) {
    asm("mov.b64 {%0,%1}, %2;" : "=f"(lo), "=f"(hi) : "l"(v));
}
__device__ __forceinline__ void fma2(u64& d, u64 a, u64 b) {
    asm("fma.rn.f32x2 %0, %1, %2, %0;" : "+l"(d) : "l"(a), "l"(b));
}
__device__ __forceinline__ void cp16(unsigned dst, const void* src) {
    asm volatile("cp.async.cg.shared.global [%0], [%1], 16;" :: "r"(dst), "l"(src));
}
__device__ __forceinline__ void cp_commit() {
    asm volatile("cp.async.commit_group;");
}
__device__ __forceinline__ void cp_wait1() {
    asm volatile("cp.async.wait_group 1;");
}
__device__ __forceinline__ void cp_wait0() {
    asm volatile("cp.async.wait_group 0;");
}

__device__ __forceinline__ float sigmoidf_(float x) {
    return 1.0f / (1.0f + __expf(-x));
}
__device__ __forceinline__ float tanhf_(float x) {
    return 1.0f - 2.0f / (__expf(2.0f * x) + 1.0f);
}

// one k (scalar x per row) against all 16 j
__device__ __forceinline__ void do_k(u64 acc[RPT][8], const float xv[RPT],
                                     const ulonglong2* __restrict__ wk) {
    ulonglong2 wa = wk[0], wb = wk[1], wc = wk[2], wd = wk[3]; // j 0..15
#pragma unroll
    for (int r = 0; r < RPT; r++) {
        u64 s = pk(xv[r], xv[r]);
        fma2(acc[r][0], s, wa.x); fma2(acc[r][1], s, wa.y);
        fma2(acc[r][2], s, wb.x); fma2(acc[r][3], s, wb.y);
        fma2(acc[r][4], s, wc.x); fma2(acc[r][5], s, wc.y);
        fma2(acc[r][6], s, wd.x); fma2(acc[r][7], s, wd.y);
    }
}

__global__ void __launch_bounds__(THREADS)
qlstm_kernel(const float* __restrict__ x, const float* __restrict__ hx,
             const float* __restrict__ cx,
             const float* __restrict__ Wf, const float* __restrict__ bf,
             const float* __restrict__ Wi, const float* __restrict__ bi,
             const float* __restrict__ Wu, const float* __restrict__ bu,
             const float* __restrict__ Wo, const float* __restrict__ bo,
             const float* __restrict__ tf, const float* __restrict__ ti,
             const float* __restrict__ tu, const float* __restrict__ to,
             float* __restrict__ out, int B)
{
    extern __shared__ float smem[];
    float* swf    = smem;                      // [260][16] j-major per k
    float* xs     = smem + SWF_F;              // [2][256][PITCH]
    float* sphase = smem + SWF_F + 2 * XS_STAGE_F;

    const int tid = threadIdx.x;
    const int row0 = blockIdx.x * ROWS_BLK;
    const float* xblk = x + (size_t)row0 * D_COLS;

    // ---- issue tiles 0,1 immediately (before weight staging) ----
    unsigned xs_s = (unsigned)__cvta_generic_to_shared(xs);
#pragma unroll
    for (int stg = 0; stg < 2; stg++) {
#pragma unroll
        for (int i = 0; i < (ROWS_BLK * TILE_K / 4) / THREADS; i++) {  // 8
            int c  = i * THREADS + tid;       // 16B-chunk id
            int rl = c >> 2, kq = c & 3;
            cp16(xs_s + (unsigned)((stg * XS_STAGE_F + rl * PITCH + kq * 4) * 4),
                 xblk + (size_t)rl * D_COLS + stg * TILE_K + kq * 4);
        }
        cp_commit();
    }

    // ---- stage weights (one-time) ----
    for (int i = tid; i < SWF_F; i += THREADS) {
        int k = i >> 4, j = i & 15;
        int g = j >> 2, w = j & 3;
        const float* W = (g == 0) ? Wf : (g == 1) ? Wi : (g == 2) ? Wu : Wo;
        swf[i] = W[w * 260 + k];
    }
    if (tid < NJ) {
        int j = tid, g = j >> 2, w = j & 3;
        const float* bb = (g == 0) ? bf : (g == 1) ? bi : (g == 2) ? bu : bo;
        const float* tt = (g == 0) ? tf : (g == 1) ? ti : (g == 2) ? tu : to;
        sphase[j] = bb[w] + tt[w];
    }

    const ulonglong2* swv2 = (const ulonglong2*)swf;  // [k][4]

    u64 acc[RPT][8];
#pragma unroll
    for (int r = 0; r < RPT; r++)
#pragma unroll
        for (int jj = 0; jj < 8; jj++) acc[r][jj] = 0ull;

    // ---- main pipelined loop over k-tiles ----
#pragma unroll 1
    for (int t = 0; t < NTILES; t++) {
        if (t == NTILES - 1) cp_wait0(); else cp_wait1();
        __syncthreads();

        const float* xb = xs + (t & 1) * XS_STAGE_F;
#pragma unroll
        for (int kq = 0; kq < 4; kq++) {
            float4 xv[RPT];
#pragma unroll
            for (int rr = 0; rr < RPT; rr++) {
                int rl = tid + THREADS * rr;
                xv[rr] = *(const float4*)(xb + rl * PITCH + kq * 4);
            }
#pragma unroll
            for (int e = 0; e < 4; e++) {
                int k = t * TILE_K + kq * 4 + e;
                const ulonglong2* wk = swv2 + (size_t)k * 4;
                float s[RPT];
#pragma unroll
                for (int rr = 0; rr < RPT; rr++)
                    s[rr] = ((const float*)&xv[rr])[e];
                do_k(acc, s, wk);
            }
        }
        __syncthreads();

        if (t + 2 < NTILES) {
            int nt = t + 2;
#pragma unroll
            for (int i = 0; i < (ROWS_BLK * TILE_K / 4) / THREADS; i++) {
                int c  = i * THREADS + tid;
                int rl = c >> 2, kq = c & 3;
                cp16(xs_s + (unsigned)(((t & 1) * XS_STAGE_F + rl * PITCH + kq * 4) * 4),
                     xblk + (size_t)rl * D_COLS + nt * TILE_K + kq * 4);
            }
            cp_commit();
        }
    }

    // ---- hx tail: k = 256..259 (coalesced across lanes) ----
    {
        float4 hv[RPT];
#pragma unroll
        for (int rr = 0; rr < RPT; rr++)
            hv[rr] = ((const float4*)hx)[row0 + tid + THREADS * rr];
#pragma unroll
        for (int e = 0; e < 4; e++) {
            const ulonglong2* wk = swv2 + (size_t)(256 + e) * 4;
            float s[RPT];
#pragma unroll
            for (int rr = 0; rr < RPT; rr++)
                s[rr] = ((const float*)&hv[rr])[e];
            do_k(acc, s, wk);
        }
    }

    // ---- epilogue per row ----
#pragma unroll
    for (int rr = 0; rr < RPT; rr++) {
        int r = row0 + tid + THREADS * rr;
        float z[NJ];
#pragma unroll
        for (int jj = 0; jj < 8; jj++) {
            float lo, hi; upk(acc[rr][jj], lo, hi);
            z[2 * jj]     = __cosf(lo + sphase[2 * jj]);
            z[2 * jj + 1] = __cosf(hi + sphase[2 * jj + 1]);
        }
        float e[NJ];
#pragma unroll
        for (int g = 0; g < 4; g++) {
            float z0 = z[g*4+0], z1 = z[g*4+1], z2 = z[g*4+2], z3 = z[g*4+3];
            float p01 = z0 * z1;
            e[g*4+0] = z1 * z2 * z3;
            e[g*4+1] = p01;
            e[g*4+2] = p01 * z2;
            e[g*4+3] = p01 * z2 * z3;
        }
        float4 cxv = ((const float4*)cx)[r];
        float cxa[4] = {cxv.x, cxv.y, cxv.z, cxv.w};
        float hn[4], cn[4];
#pragma unroll
        for (int w = 0; w < 4; w++) {
            float fv = sigmoidf_(e[0*4+w]);
            float iv = sigmoidf_(e[1*4+w]);
            float gv = tanhf_(e[2*4+w]);
            float ov = sigmoidf_(e[3*4+w]);
            float c = fv * cxa[w] + iv * gv;
            cn[w] = c;
            hn[w] = ov * tanhf_(c);
        }
        ((float4*)out)[r] = make_float4(hn[0], hn[1], hn[2], hn[3]);
        ((float4*)(out + (size_t)B * 4))[r] = make_float4(cn[0], cn[1], cn[2], cn[3]);
    }
}

extern "C" void kernel_launch(void* const* d_in, const int* in_sizes, int n_in,
                              void* d_out, int out_size) {
    const float* x  = (const float*)d_in[0];
    const float* hx = (const float*)d_in[1];
    const float* cx = (const float*)d_in[2];
    const float* Wf = (const float*)d_in[3];
    const float* bf = (const float*)d_in[4];
    const float* Wi = (const float*)d_in[5];
    const float* bi = (const float*)d_in[6];
    const float* Wu = (const float*)d_in[7];
    const float* bu = (const float*)d_in[8];
    const float* Wo = (const float*)d_in[9];
    const float* bo = (const float*)d_in[10];
    const float* tf = (const float*)d_in[11];
    const float* ti = (const float*)d_in[12];
    const float* tu = (const float*)d_in[13];
    const float* to = (const float*)d_in[14];
    float* out = (float*)d_out;

    int B = in_sizes[0] / D_COLS;                 // 131072
    int grid = (B + ROWS_BLK - 1) / ROWS_BLK;     // 512

    cudaFuncSetAttribute(qlstm_kernel,
                         cudaFuncAttributeMaxDynamicSharedMemorySize, SMEM_BYTES);

    qlstm_kernel<<<grid, THREADS, SMEM_BYTES>>>(
        x, hx, cx, Wf, bf, Wi, bi, Wu, bu, Wo, bo,
        tf, ti, tu, to, out, B);
}

// round 6
// speedup vs baseline: 1.2168x; 1.2168x over previous
#include <cuda_runtime.h>

// _QuantumLSTMCell: analytic collapse of the 4-qubit circuit.
// angles = comb @ W^T + b ; z_w = cos(angle_w + th_w)
// E0 = z1 z2 z3 ; E1 = z0 z1 ; E2 = z0 z1 z2 ; E3 = z0 z1 z2 z3
// f,i,o = sigmoid(E), g = tanh(E_u); c' = f*cx + i*g; h' = o*tanh(c')
// out = [h_new (B*4) | c_new (B*4)]
//
// R6: per-warp-private double-buffered cp.async pipelines (NO block barriers
// in the main loop -- only __syncwarp), RPT=2, TILE_K=8, pitch-12
// conflict-free x tiles. One __syncthreads total (weight staging).

#define THREADS 128
#define WARPS 4
#define RPT 2
#define ROWS_WARP 64                 // 32 lanes * RPT
#define ROWS_BLK (WARPS * ROWS_WARP) // 256
#define D_COLS 256
#define NJ 16
#define TILE_K 8
#define NTILES (D_COLS / TILE_K)     // 32
#define PITCH 12                     // floats per staged row (12 % 8 == 4 -> conflict-free)
#define XS_WARP_F (ROWS_WARP * PITCH)    // 768 floats per warp per stage
#define SWF_F (260 * NJ)             // 4160 floats
#define SMEM_FLOATS (SWF_F + WARPS * 2 * XS_WARP_F + NJ)
#define SMEM_BYTES (SMEM_FLOATS * 4) // 41,280 B -> ~4-5 CTAs/SM

typedef unsigned long long u64;

__device__ __forceinline__ u64 pk(float lo, float hi) {
    u64 r; asm("mov.b64 %0, {%1,%2};" : "=l"(r) : "f"(lo), "f"(hi)); return r;
}
__device__ __forceinline__ void upk(u64 v, float& lo, float& hi) {
    asm("mov.b64 {%0,%1}, %2;" : "=f"(lo), "=f"(hi) : "l"(v));
}
__device__ __forceinline__ void fma2(u64& d, u64 a, u64 b) {
    asm("fma.rn.f32x2 %0, %1, %2, %0;" : "+l"(d) : "l"(a), "l"(b));
}
__device__ __forceinline__ void cp16(unsigned dst, const void* src) {
    asm volatile("cp.async.cg.shared.global [%0], [%1], 16;" :: "r"(dst), "l"(src));
}
__device__ __forceinline__ void cp_commit() {
    asm volatile("cp.async.commit_group;");
}
__device__ __forceinline__ void cp_wait1() {
    asm volatile("cp.async.wait_group 1;");
}
__device__ __forceinline__ void cp_wait0() {
    asm volatile("cp.async.wait_group 0;");
}

__device__ __forceinline__ float sigmoidf_(float x) {
    return 1.0f / (1.0f + __expf(-x));
}
__device__ __forceinline__ float tanhf_(float x) {
    return 1.0f - 2.0f / (__expf(2.0f * x) + 1.0f);
}

// one k (scalar x per row) against all 16 j
__device__ __forceinline__ void do_k(u64 acc[RPT][8], const float xv[RPT],
                                     const ulonglong2* __restrict__ wk) {
    ulonglong2 wa = wk[0], wb = wk[1], wc = wk[2], wd = wk[3]; // j 0..15
#pragma unroll
    for (int r = 0; r < RPT; r++) {
        u64 s = pk(xv[r], xv[r]);
        fma2(acc[r][0], s, wa.x); fma2(acc[r][1], s, wa.y);
        fma2(acc[r][2], s, wb.x); fma2(acc[r][3], s, wb.y);
        fma2(acc[r][4], s, wc.x); fma2(acc[r][5], s, wc.y);
        fma2(acc[r][6], s, wd.x); fma2(acc[r][7], s, wd.y);
    }
}

__global__ void __launch_bounds__(THREADS, 4)
qlstm_kernel(const float* __restrict__ x, const float* __restrict__ hx,
             const float* __restrict__ cx,
             const float* __restrict__ Wf, const float* __restrict__ bf,
             const float* __restrict__ Wi, const float* __restrict__ bi,
             const float* __restrict__ Wu, const float* __restrict__ bu,
             const float* __restrict__ Wo, const float* __restrict__ bo,
             const float* __restrict__ tf, const float* __restrict__ ti,
             const float* __restrict__ tu, const float* __restrict__ to,
             float* __restrict__ out, int B)
{
    extern __shared__ float smem[];
    float* swf    = smem;                              // [260][16] j-major
    float* xs     = smem + SWF_F;                      // [4 warps][2 stages][768]
    float* sphase = smem + SWF_F + WARPS * 2 * XS_WARP_F;

    const int tid  = threadIdx.x;
    const int wid  = tid >> 5;
    const int lane = tid & 31;

    const int row0 = blockIdx.x * ROWS_BLK + wid * ROWS_WARP;  // warp's first row
    const float* xw = x + (size_t)row0 * D_COLS;

    float* xs_w = xs + wid * (2 * XS_WARP_F);
    unsigned xs_s = (unsigned)__cvta_generic_to_shared(xs_w);

    // ---- issue this warp's stages 0,1 (each: 64 rows x 8 k = 2 KB) ----
#pragma unroll
    for (int stg = 0; stg < 2; stg++) {
#pragma unroll
        for (int i = 0; i < 4; i++) {
            int c  = lane + 32 * i;        // 0..127 16B-chunks
            int rl = c >> 1, kq = c & 1;
            cp16(xs_s + (unsigned)((stg * XS_WARP_F + rl * PITCH + kq * 4) * 4),
                 xw + (size_t)rl * D_COLS + stg * TILE_K + kq * 4);
        }
        cp_commit();
    }

    // ---- stage weights (block-cooperative, one-time) ----
    for (int i = tid; i < SWF_F; i += THREADS) {
        int k = i >> 4, j = i & 15;
        int g = j >> 2, w = j & 3;
        const float* W = (g == 0) ? Wf : (g == 1) ? Wi : (g == 2) ? Wu : Wo;
        swf[i] = W[w * 260 + k];
    }
    if (tid < NJ) {
        int j = tid, g = j >> 2, w = j & 3;
        const float* bb = (g == 0) ? bf : (g == 1) ? bi : (g == 2) ? bu : bo;
        const float* tt = (g == 0) ? tf : (g == 1) ? ti : (g == 2) ? tu : to;
        sphase[j] = bb[w] + tt[w];
    }
    __syncthreads();   // the ONLY block barrier

    const ulonglong2* swv2 = (const ulonglong2*)swf;  // [k][4]

    u64 acc[RPT][8];
#pragma unroll
    for (int r = 0; r < RPT; r++)
#pragma unroll
        for (int jj = 0; jj < 8; jj++) acc[r][jj] = 0ull;

    // ---- warp-private pipelined loop over k-tiles ----
#pragma unroll 1
    for (int t = 0; t < NTILES; t++) {
        if (t == NTILES - 1) cp_wait0(); else cp_wait1();
        __syncwarp();   // all lanes' own-group waits done -> tile fully visible

        const float* xb = xs_w + (t & 1) * XS_WARP_F;
#pragma unroll
        for (int kq = 0; kq < 2; kq++) {
            float4 xv[RPT];
#pragma unroll
            for (int rr = 0; rr < RPT; rr++)
                xv[rr] = *(const float4*)(xb + (lane + 32 * rr) * PITCH + kq * 4);
#pragma unroll
            for (int e = 0; e < 4; e++) {
                int k = t * TILE_K + kq * 4 + e;
                const ulonglong2* wk = swv2 + (size_t)k * 4;
                float s[RPT];
#pragma unroll
                for (int rr = 0; rr < RPT; rr++)
                    s[rr] = ((const float*)&xv[rr])[e];
                do_k(acc, s, wk);
            }
        }
        __syncwarp();   // all lanes done reading before overwrite

        if (t + 2 < NTILES) {
            int nt = t + 2;
#pragma unroll
            for (int i = 0; i < 4; i++) {
                int c  = lane + 32 * i;
                int rl = c >> 1, kq = c & 1;
                cp16(xs_s + (unsigned)(((t & 1) * XS_WARP_F + rl * PITCH + kq * 4) * 4),
                     xw + (size_t)rl * D_COLS + nt * TILE_K + kq * 4);
            }
            cp_commit();
        }
    }

    // ---- hx tail: k = 256..259 (coalesced across lanes) ----
    {
        float4 hv[RPT];
#pragma unroll
        for (int rr = 0; rr < RPT; rr++)
            hv[rr] = ((const float4*)hx)[row0 + lane + 32 * rr];
#pragma unroll
        for (int e = 0; e < 4; e++) {
            const ulonglong2* wk = swv2 + (size_t)(256 + e) * 4;
            float s[RPT];
#pragma unroll
            for (int rr = 0; rr < RPT; rr++)
                s[rr] = ((const float*)&hv[rr])[e];
            do_k(acc, s, wk);
        }
    }

    // ---- epilogue per row ----
#pragma unroll
    for (int rr = 0; rr < RPT; rr++) {
        int r = row0 + lane + 32 * rr;
        float z[NJ];
#pragma unroll
        for (int jj = 0; jj < 8; jj++) {
            float lo, hi; upk(acc[rr][jj], lo, hi);
            z[2 * jj]     = __cosf(lo + sphase[2 * jj]);
            z[2 * jj + 1] = __cosf(hi + sphase[2 * jj + 1]);
        }
        float e[NJ];
#pragma unroll
        for (int g = 0; g < 4; g++) {
            float z0 = z[g*4+0], z1 = z[g*4+1], z2 = z[g*4+2], z3 = z[g*4+3];
            float p01 = z0 * z1;
            e[g*4+0] = z1 * z2 * z3;
            e[g*4+1] = p01;
            e[g*4+2] = p01 * z2;
            e[g*4+3] = p01 * z2 * z3;
        }
        float4 cxv = ((const float4*)cx)[r];
        float cxa[4] = {cxv.x, cxv.y, cxv.z, cxv.w};
        float hn[4], cn[4];
#pragma unroll
        for (int w = 0; w < 4; w++) {
            float fv = sigmoidf_(e[0*4+w]);
            float iv = sigmoidf_(e[1*4+w]);
            float gv = tanhf_(e[2*4+w]);
            float ov = sigmoidf_(e[3*4+w]);
            float c = fv * cxa[w] + iv * gv;
            cn[w] = c;
            hn[w] = ov * tanhf_(c);
        }
        ((float4*)out)[r] = make_float4(hn[0], hn[1], hn[2], hn[3]);
        ((float4*)(out + (size_t)B * 4))[r] = make_float4(cn[0], cn[1], cn[2], cn[3]);
    }
}

extern "C" void kernel_launch(void* const* d_in, const int* in_sizes, int n_in,
                              void* d_out, int out_size) {
    const float* x  = (const float*)d_in[0];
    const float* hx = (const float*)d_in[1];
    const float* cx = (const float*)d_in[2];
    const float* Wf = (const float*)d_in[3];
    const float* bf = (const float*)d_in[4];
    const float* Wi = (const float*)d_in[5];
    const float* bi = (const float*)d_in[6];
    const float* Wu = (const float*)d_in[7];
    const float* bu = (const float*)d_in[8];
    const float* Wo = (const float*)d_in[9];
    const float* bo = (const float*)d_in[10];
    const float* tf = (const float*)d_in[11];
    const float* ti = (const float*)d_in[12];
    const float* tu = (const float*)d_in[13];
    const float* to = (const float*)d_in[14];
    float* out = (float*)d_out;

    int B = in_sizes[0] / D_COLS;                 // 131072
    int grid = (B + ROWS_BLK - 1) / ROWS_BLK;     // 512

    cudaFuncSetAttribute(qlstm_kernel,
                         cudaFuncAttributeMaxDynamicSharedMemorySize, SMEM_BYTES);

    qlstm_kernel<<<grid, THREADS, SMEM_BYTES>>>(
        x, hx, cx, Wf, bf, Wi, bi, Wu, bu, Wo, bo,
        tf, ti, tu, to, out, B);
}